// round 1
// baseline (speedup 1.0000x reference)
#include <cuda_runtime.h>
#include <math.h>

#define BB 2
#define SS 2048
#define TT (BB*SS)
#define DD 1024
#define HH 16
#define DHH 64
#define DM 4096

// ---------------- scratch (device globals; no runtime allocation) ----------------
__device__ float g_normx[TT*DD];
__device__ float g_q[TT*DD];
__device__ float g_k[TT*DD];
__device__ float g_v[TT*DD];
__device__ float g_attn[TT*DD];
__device__ float g_x1[TT*DD];
__device__ float g_h[TT*DD];
__device__ float g_h1[(size_t)TT*DM];

// ---------------- LayerNorm: one block per token ----------------
__global__ void __launch_bounds__(256) ln_kernel(const float* __restrict__ x,
                                                 const float* __restrict__ g,
                                                 const float* __restrict__ be,
                                                 float* __restrict__ out) {
    int t = blockIdx.x;
    int tid = threadIdx.x;
    float4 v = ((const float4*)(x + (size_t)t * DD))[tid];
    float s  = v.x + v.y + v.z + v.w;
    float ss = v.x*v.x + v.y*v.y + v.z*v.z + v.w*v.w;
    #pragma unroll
    for (int o = 16; o; o >>= 1) {
        s  += __shfl_xor_sync(0xffffffffu, s, o);
        ss += __shfl_xor_sync(0xffffffffu, ss, o);
    }
    __shared__ float ws[8], wss[8];
    int w = tid >> 5, ln = tid & 31;
    if (ln == 0) { ws[w] = s; wss[w] = ss; }
    __syncthreads();
    float ts = 0.f, tss = 0.f;
    #pragma unroll
    for (int i = 0; i < 8; i++) { ts += ws[i]; tss += wss[i]; }
    float mu  = ts * (1.0f / DD);
    float var = tss * (1.0f / DD) - mu * mu;
    float rs  = rsqrtf(var + 1e-5f);
    float4 gv = ((const float4*)g)[tid];
    float4 bv = ((const float4*)be)[tid];
    float4 o;
    o.x = (v.x - mu) * rs * gv.x + bv.x;
    o.y = (v.y - mu) * rs * gv.y + bv.y;
    o.z = (v.z - mu) * rs * gv.z + bv.z;
    o.w = (v.w - mu) * rs * gv.w + bv.w;
    ((float4*)(out + (size_t)t * DD))[tid] = o;
}

// ---------------- GEMM: C[M,N] = A[M,K] @ B[K,N] (+bias)(+relu)(+res) ----------------
// HEADB: B is [H][K][64] per-head layout, logical column j -> W[j>>6][k][j&63]
template<bool HEADB, bool RELU>
__global__ void __launch_bounds__(256) gemm_kernel(
    const float* __restrict__ A, const float* __restrict__ Bm,
    float* __restrict__ C, int M, int N, int K,
    const float* __restrict__ bias, const float* __restrict__ res)
{
    __shared__ float As[8][132];   // transposed, padded (conflict-free)
    __shared__ float Bs[8][128];
    const int tid = threadIdx.x;
    const int bm = blockIdx.y, bn = blockIdx.x;

    const int arow = tid >> 1;          // 0..127
    const int acol = (tid & 1) << 2;    // 0 or 4
    const float* Ap = A + (size_t)(bm * 128 + arow) * K + acol;

    const int brow = tid >> 5;          // 0..7
    const int bcol = (tid & 31) << 2;   // 0..124
    const int gcol = bn * 128 + bcol;
    const float* Bp;
    int ldb;
    if (HEADB) { ldb = 64; Bp = Bm + (size_t)(gcol >> 6) * K * 64 + (gcol & 63) + (size_t)brow * 64; }
    else       { ldb = N;  Bp = Bm + (size_t)brow * N + gcol; }

    const int ra = (tid >> 4) << 2;     // 0..60
    const int cb = (tid & 15) << 2;     // 0..60

    float acc[8][8];
    #pragma unroll
    for (int i = 0; i < 8; i++)
        #pragma unroll
        for (int j = 0; j < 8; j++) acc[i][j] = 0.f;

    for (int k0 = 0; k0 < K; k0 += 8) {
        float4 av = *(const float4*)(Ap + k0);
        As[acol + 0][arow] = av.x;
        As[acol + 1][arow] = av.y;
        As[acol + 2][arow] = av.z;
        As[acol + 3][arow] = av.w;
        *(float4*)&Bs[brow][bcol] = *(const float4*)(Bp + (size_t)k0 * ldb);
        __syncthreads();
        #pragma unroll
        for (int kk = 0; kk < 8; kk++) {
            float4 a0 = *(const float4*)&As[kk][ra];
            float4 a1 = *(const float4*)&As[kk][ra + 64];
            float4 b0 = *(const float4*)&Bs[kk][cb];
            float4 b1 = *(const float4*)&Bs[kk][cb + 64];
            float a[8] = {a0.x,a0.y,a0.z,a0.w,a1.x,a1.y,a1.z,a1.w};
            float b[8] = {b0.x,b0.y,b0.z,b0.w,b1.x,b1.y,b1.z,b1.w};
            #pragma unroll
            for (int i = 0; i < 8; i++)
                #pragma unroll
                for (int j = 0; j < 8; j++)
                    acc[i][j] = fmaf(a[i], b[j], acc[i][j]);
        }
        __syncthreads();
    }

    #pragma unroll
    for (int i = 0; i < 8; i++) {
        int r = bm * 128 + ra + (i < 4 ? i : 60 + i);
        #pragma unroll
        for (int jh = 0; jh < 2; jh++) {
            int c = bn * 128 + cb + jh * 64;
            float4 v;
            v.x = acc[i][jh*4+0]; v.y = acc[i][jh*4+1];
            v.z = acc[i][jh*4+2]; v.w = acc[i][jh*4+3];
            if (bias) {
                float4 bb = *(const float4*)(bias + c);
                v.x += bb.x; v.y += bb.y; v.z += bb.z; v.w += bb.w;
            }
            if (RELU) {
                v.x = fmaxf(v.x, 0.f); v.y = fmaxf(v.y, 0.f);
                v.z = fmaxf(v.z, 0.f); v.w = fmaxf(v.w, 0.f);
            }
            if (res) {
                float4 rv = *(const float4*)(res + (size_t)r * N + c);
                v.x += rv.x; v.y += rv.y; v.z += rv.z; v.w += rv.w;
            }
            *(float4*)(C + (size_t)r * N + c) = v;
        }
    }
}

// ---------------- Flash-style attention, fp32, BQ=BK=64 ----------------
// Q/K/V layout: [T][1024] with columns h*64..h*64+63 per head.
#define ATT_LD 68
__global__ void __launch_bounds__(256) attn_kernel(
    const float* __restrict__ Q, const float* __restrict__ Km,
    const float* __restrict__ V, float* __restrict__ O)
{
    extern __shared__ float sm[];
    float* Qs  = sm;                 // 64 x 68
    float* KPs = sm + 64 * ATT_LD;   // K tile, later reused for P
    float* Vs  = sm + 2 * 64 * ATT_LD;

    const int tid = threadIdx.x;
    const int qb = blockIdx.x, bh = blockIdx.y;
    const int b = bh >> 4, h = bh & 15;
    const int colbase = h * 64;
    const size_t rowbase = (size_t)b * SS;

    #pragma unroll
    for (int i = 0; i < 4; i++) {
        int idx = tid + i * 256;
        int row = idx >> 4;
        int c4  = (idx & 15) << 2;
        float4 qv = *(const float4*)(Q + (rowbase + qb*64 + row) * 1024 + colbase + c4);
        qv.x *= 0.125f; qv.y *= 0.125f; qv.z *= 0.125f; qv.w *= 0.125f;  // 1/sqrt(64)
        *(float4*)&Qs[row * ATT_LD + c4] = qv;
    }

    const int ty = tid >> 4, tx = tid & 15;
    const int q0 = ty << 2;
    float m[4] = {-1e30f, -1e30f, -1e30f, -1e30f};
    float l[4] = {0.f, 0.f, 0.f, 0.f};
    float4 acc[4];
    #pragma unroll
    for (int i = 0; i < 4; i++) acc[i] = make_float4(0.f, 0.f, 0.f, 0.f);

    __syncthreads();

    for (int kb = 0; kb < SS / 64; kb++) {
        #pragma unroll
        for (int i = 0; i < 4; i++) {
            int idx = tid + i * 256;
            int row = idx >> 4;
            int c4  = (idx & 15) << 2;
            size_t gro = (rowbase + kb*64 + row) * 1024 + colbase + c4;
            *(float4*)&KPs[row * ATT_LD + c4] = *(const float4*)(Km + gro);
            *(float4*)&Vs [row * ATT_LD + c4] = *(const float4*)(V  + gro);
        }
        __syncthreads();

        // S = Q K^T for this thread's 4x4 patch
        float s[4][4] = {};
        #pragma unroll
        for (int dv = 0; dv < 16; dv++) {
            float4 qv[4], kv[4];
            #pragma unroll
            for (int i = 0; i < 4; i++) qv[i] = *(const float4*)&Qs[(q0 + i) * ATT_LD + dv * 4];
            #pragma unroll
            for (int j = 0; j < 4; j++) kv[j] = *(const float4*)&KPs[(tx*4 + j) * ATT_LD + dv * 4];
            #pragma unroll
            for (int i = 0; i < 4; i++)
                #pragma unroll
                for (int j = 0; j < 4; j++)
                    s[i][j] += qv[i].x*kv[j].x + qv[i].y*kv[j].y + qv[i].z*kv[j].z + qv[i].w*kv[j].w;
        }
        __syncthreads();   // all threads done reading K tile

        // online softmax; write P into KPs
        #pragma unroll
        for (int i = 0; i < 4; i++) {
            float mx = fmaxf(fmaxf(s[i][0], s[i][1]), fmaxf(s[i][2], s[i][3]));
            #pragma unroll
            for (int o = 8; o; o >>= 1) mx = fmaxf(mx, __shfl_xor_sync(0xffffffffu, mx, o, 16));
            float mn = fmaxf(m[i], mx);
            float co = __expf(m[i] - mn);
            m[i] = mn;
            float p0 = __expf(s[i][0] - mn);
            float p1 = __expf(s[i][1] - mn);
            float p2 = __expf(s[i][2] - mn);
            float p3 = __expf(s[i][3] - mn);
            float rs = p0 + p1 + p2 + p3;
            #pragma unroll
            for (int o = 8; o; o >>= 1) rs += __shfl_xor_sync(0xffffffffu, rs, o, 16);
            l[i] = l[i] * co + rs;
            acc[i].x *= co; acc[i].y *= co; acc[i].z *= co; acc[i].w *= co;
            *(float4*)&KPs[(q0 + i) * ATT_LD + tx * 4] = make_float4(p0, p1, p2, p3);
        }
        __syncthreads();

        // O += P V
        #pragma unroll
        for (int j4 = 0; j4 < 16; j4++) {
            float4 vr[4];
            #pragma unroll
            for (int jj = 0; jj < 4; jj++)
                vr[jj] = *(const float4*)&Vs[(j4*4 + jj) * ATT_LD + tx * 4];
            #pragma unroll
            for (int i = 0; i < 4; i++) {
                float4 pv = *(const float4*)&KPs[(q0 + i) * ATT_LD + j4 * 4];
                acc[i].x += pv.x*vr[0].x + pv.y*vr[1].x + pv.z*vr[2].x + pv.w*vr[3].x;
                acc[i].y += pv.x*vr[0].y + pv.y*vr[1].y + pv.z*vr[2].y + pv.w*vr[3].y;
                acc[i].z += pv.x*vr[0].z + pv.y*vr[1].z + pv.z*vr[2].z + pv.w*vr[3].z;
                acc[i].w += pv.x*vr[0].w + pv.y*vr[1].w + pv.z*vr[2].w + pv.w*vr[3].w;
            }
        }
        __syncthreads();
    }

    #pragma unroll
    for (int i = 0; i < 4; i++) {
        float inv = 1.0f / l[i];
        float4 o = acc[i];
        o.x *= inv; o.y *= inv; o.z *= inv; o.w *= inv;
        *(float4*)(O + (rowbase + qb*64 + q0 + i) * 1024 + colbase + tx * 4) = o;
    }
}

// ---------------- host launcher ----------------
extern "C" void kernel_launch(void* const* d_in, const int* in_sizes, int n_in,
                              void* d_out, int out_size) {
    const float* x    = (const float*)d_in[0];
    const float* WQ   = (const float*)d_in[1];
    const float* WK   = (const float*)d_in[2];
    const float* WV   = (const float*)d_in[3];
    const float* WO   = (const float*)d_in[4];
    const float* ln1g = (const float*)d_in[5];
    const float* ln1b = (const float*)d_in[6];
    const float* ln2g = (const float*)d_in[7];
    const float* ln2b = (const float*)d_in[8];
    const float* w1   = (const float*)d_in[9];
    const float* b1   = (const float*)d_in[10];
    const float* w2   = (const float*)d_in[11];
    const float* b2   = (const float*)d_in[12];
    float* out = (float*)d_out;

    float *normx, *q, *k, *v, *attn, *x1, *hb, *h1;
    cudaGetSymbolAddress((void**)&normx, g_normx);
    cudaGetSymbolAddress((void**)&q,     g_q);
    cudaGetSymbolAddress((void**)&k,     g_k);
    cudaGetSymbolAddress((void**)&v,     g_v);
    cudaGetSymbolAddress((void**)&attn,  g_attn);
    cudaGetSymbolAddress((void**)&x1,    g_x1);
    cudaGetSymbolAddress((void**)&hb,    g_h);
    cudaGetSymbolAddress((void**)&h1,    g_h1);

    const int ATT_SMEM = 3 * 64 * ATT_LD * 4;  // 52224 bytes
    cudaFuncSetAttribute(attn_kernel, cudaFuncAttributeMaxDynamicSharedMemorySize, ATT_SMEM);

    // 1) LN1
    ln_kernel<<<TT, 256>>>(x, ln1g, ln1b, normx);

    // 2) QKV projections (per-head gathered B)
    dim3 gqkv(DD / 128, TT / 128);
    gemm_kernel<true,  false><<<gqkv, 256>>>(normx, WQ, q, TT, DD, DD, nullptr, nullptr);
    gemm_kernel<true,  false><<<gqkv, 256>>>(normx, WK, k, TT, DD, DD, nullptr, nullptr);
    gemm_kernel<true,  false><<<gqkv, 256>>>(normx, WV, v, TT, DD, DD, nullptr, nullptr);

    // 3) attention
    attn_kernel<<<dim3(SS / 64, BB * HH), 256, ATT_SMEM>>>(q, k, v, attn);

    // 4) O projection + residual -> x1
    gemm_kernel<false, false><<<dim3(DD / 128, TT / 128), 256>>>(attn, WO, x1, TT, DD, DD, nullptr, x);

    // 5) LN2
    ln_kernel<<<TT, 256>>>(x1, ln2g, ln2b, hb);

    // 6) MLP1: relu(h @ w1 + b1)
    gemm_kernel<false, true ><<<dim3(DM / 128, TT / 128), 256>>>(hb, w1, h1, TT, DM, DD, b1, nullptr);

    // 7) MLP2: x1 + (h1 @ w2 + b2) -> out
    gemm_kernel<false, false><<<dim3(DD / 128, TT / 128), 256>>>(h1, w2, out, TT, DD, DM, b2, x1);
}

// round 2
// speedup vs baseline: 1.0007x; 1.0007x over previous
#include <cuda_runtime.h>
#include <math.h>

#define BB 2
#define SS 2048
#define TT (BB*SS)
#define DD 1024
#define HH 16
#define DHH 64
#define DM 4096

// ---------------- scratch (device globals; no runtime allocation) ----------------
__device__ float g_normx[TT*DD];
__device__ float g_q[TT*DD];
__device__ float g_k[TT*DD];
__device__ float g_v[TT*DD];
__device__ float g_attn[TT*DD];
__device__ float g_x1[TT*DD];
__device__ float g_h[TT*DD];
__device__ float g_h1[(size_t)TT*DM];

// ---------------- LayerNorm: one block per token ----------------
__global__ void __launch_bounds__(256) ln_kernel(const float* __restrict__ x,
                                                 const float* __restrict__ g,
                                                 const float* __restrict__ be,
                                                 float* __restrict__ out) {
    int t = blockIdx.x;
    int tid = threadIdx.x;
    float4 v = ((const float4*)(x + (size_t)t * DD))[tid];
    float s  = v.x + v.y + v.z + v.w;
    float ss = v.x*v.x + v.y*v.y + v.z*v.z + v.w*v.w;
    #pragma unroll
    for (int o = 16; o; o >>= 1) {
        s  += __shfl_xor_sync(0xffffffffu, s, o);
        ss += __shfl_xor_sync(0xffffffffu, ss, o);
    }
    __shared__ float ws[8], wss[8];
    int w = tid >> 5, ln = tid & 31;
    if (ln == 0) { ws[w] = s; wss[w] = ss; }
    __syncthreads();
    float ts = 0.f, tss = 0.f;
    #pragma unroll
    for (int i = 0; i < 8; i++) { ts += ws[i]; tss += wss[i]; }
    float mu  = ts * (1.0f / DD);
    float var = tss * (1.0f / DD) - mu * mu;
    float rs  = rsqrtf(var + 1e-5f);
    float4 gv = ((const float4*)g)[tid];
    float4 bv = ((const float4*)be)[tid];
    float4 o;
    o.x = (v.x - mu) * rs * gv.x + bv.x;
    o.y = (v.y - mu) * rs * gv.y + bv.y;
    o.z = (v.z - mu) * rs * gv.z + bv.z;
    o.w = (v.w - mu) * rs * gv.w + bv.w;
    ((float4*)(out + (size_t)t * DD))[tid] = o;
}

// ---------------- GEMM: C[M,N] = A[M,K] @ B[K,N] (+bias)(+relu)(+res) ----------------
// HEADB: B is [H][K][64] per-head layout, logical column j -> W[j>>6][k][j&63]
template<bool HEADB, bool RELU>
__global__ void __launch_bounds__(256) gemm_kernel(
    const float* __restrict__ A, const float* __restrict__ Bm,
    float* __restrict__ C, int M, int N, int K,
    const float* __restrict__ bias, const float* __restrict__ res)
{
    __shared__ float As[8][132];   // transposed, padded (conflict-free)
    __shared__ float Bs[8][128];
    const int tid = threadIdx.x;
    const int bm = blockIdx.y, bn = blockIdx.x;

    const int arow = tid >> 1;          // 0..127
    const int acol = (tid & 1) << 2;    // 0 or 4
    const float* Ap = A + (size_t)(bm * 128 + arow) * K + acol;

    const int brow = tid >> 5;          // 0..7
    const int bcol = (tid & 31) << 2;   // 0..124
    const int gcol = bn * 128 + bcol;
    const float* Bp;
    int ldb;
    if (HEADB) { ldb = 64; Bp = Bm + (size_t)(gcol >> 6) * K * 64 + (gcol & 63) + (size_t)brow * 64; }
    else       { ldb = N;  Bp = Bm + (size_t)brow * N + gcol; }

    const int ra = (tid >> 4) << 2;     // 0..60
    const int cb = (tid & 15) << 2;     // 0..60

    float acc[8][8];
    #pragma unroll
    for (int i = 0; i < 8; i++)
        #pragma unroll
        for (int j = 0; j < 8; j++) acc[i][j] = 0.f;

    for (int k0 = 0; k0 < K; k0 += 8) {
        float4 av = *(const float4*)(Ap + k0);
        As[acol + 0][arow] = av.x;
        As[acol + 1][arow] = av.y;
        As[acol + 2][arow] = av.z;
        As[acol + 3][arow] = av.w;
        *(float4*)&Bs[brow][bcol] = *(const float4*)(Bp + (size_t)k0 * ldb);
        __syncthreads();
        #pragma unroll
        for (int kk = 0; kk < 8; kk++) {
            float4 a0 = *(const float4*)&As[kk][ra];
            float4 a1 = *(const float4*)&As[kk][ra + 64];
            float4 b0 = *(const float4*)&Bs[kk][cb];
            float4 b1 = *(const float4*)&Bs[kk][cb + 64];
            float a[8] = {a0.x,a0.y,a0.z,a0.w,a1.x,a1.y,a1.z,a1.w};
            float b[8] = {b0.x,b0.y,b0.z,b0.w,b1.x,b1.y,b1.z,b1.w};
            #pragma unroll
            for (int i = 0; i < 8; i++)
                #pragma unroll
                for (int j = 0; j < 8; j++)
                    acc[i][j] = fmaf(a[i], b[j], acc[i][j]);
        }
        __syncthreads();
    }

    #pragma unroll
    for (int i = 0; i < 8; i++) {
        int r = bm * 128 + ra + (i < 4 ? i : 60 + i);
        #pragma unroll
        for (int jh = 0; jh < 2; jh++) {
            int c = bn * 128 + cb + jh * 64;
            float4 v;
            v.x = acc[i][jh*4+0]; v.y = acc[i][jh*4+1];
            v.z = acc[i][jh*4+2]; v.w = acc[i][jh*4+3];
            if (bias) {
                float4 bb = *(const float4*)(bias + c);
                v.x += bb.x; v.y += bb.y; v.z += bb.z; v.w += bb.w;
            }
            if (RELU) {
                v.x = fmaxf(v.x, 0.f); v.y = fmaxf(v.y, 0.f);
                v.z = fmaxf(v.z, 0.f); v.w = fmaxf(v.w, 0.f);
            }
            if (res) {
                float4 rv = *(const float4*)(res + (size_t)r * N + c);
                v.x += rv.x; v.y += rv.y; v.z += rv.z; v.w += rv.w;
            }
            *(float4*)(C + (size_t)r * N + c) = v;
        }
    }
}

// ---------------- Flash-style attention, fp32, BQ=BK=64 ----------------
// Q/K/V layout: [T][1024] with columns h*64..h*64+63 per head.
#define ATT_LD 68
__global__ void __launch_bounds__(256) attn_kernel(
    const float* __restrict__ Q, const float* __restrict__ Km,
    const float* __restrict__ V, float* __restrict__ O)
{
    extern __shared__ float sm[];
    float* Qs  = sm;                 // 64 x 68
    float* KPs = sm + 64 * ATT_LD;   // K tile, later reused for P
    float* Vs  = sm + 2 * 64 * ATT_LD;

    const int tid = threadIdx.x;
    const int qb = blockIdx.x, bh = blockIdx.y;
    const int b = bh >> 4, h = bh & 15;
    const int colbase = h * 64;
    const size_t rowbase = (size_t)b * SS;

    #pragma unroll
    for (int i = 0; i < 4; i++) {
        int idx = tid + i * 256;
        int row = idx >> 4;
        int c4  = (idx & 15) << 2;
        float4 qv = *(const float4*)(Q + (rowbase + qb*64 + row) * 1024 + colbase + c4);
        qv.x *= 0.125f; qv.y *= 0.125f; qv.z *= 0.125f; qv.w *= 0.125f;  // 1/sqrt(64)
        *(float4*)&Qs[row * ATT_LD + c4] = qv;
    }

    const int ty = tid >> 4, tx = tid & 15;
    const int q0 = ty << 2;
    float m[4] = {-1e30f, -1e30f, -1e30f, -1e30f};
    float l[4] = {0.f, 0.f, 0.f, 0.f};
    float4 acc[4];
    #pragma unroll
    for (int i = 0; i < 4; i++) acc[i] = make_float4(0.f, 0.f, 0.f, 0.f);

    __syncthreads();

    for (int kb = 0; kb < SS / 64; kb++) {
        #pragma unroll
        for (int i = 0; i < 4; i++) {
            int idx = tid + i * 256;
            int row = idx >> 4;
            int c4  = (idx & 15) << 2;
            size_t gro = (rowbase + kb*64 + row) * 1024 + colbase + c4;
            *(float4*)&KPs[row * ATT_LD + c4] = *(const float4*)(Km + gro);
            *(float4*)&Vs [row * ATT_LD + c4] = *(const float4*)(V  + gro);
        }
        __syncthreads();

        // S = Q K^T for this thread's 4x4 patch
        float s[4][4] = {};
        #pragma unroll
        for (int dv = 0; dv < 16; dv++) {
            float4 qv[4], kv[4];
            #pragma unroll
            for (int i = 0; i < 4; i++) qv[i] = *(const float4*)&Qs[(q0 + i) * ATT_LD + dv * 4];
            #pragma unroll
            for (int j = 0; j < 4; j++) kv[j] = *(const float4*)&KPs[(tx*4 + j) * ATT_LD + dv * 4];
            #pragma unroll
            for (int i = 0; i < 4; i++)
                #pragma unroll
                for (int j = 0; j < 4; j++)
                    s[i][j] += qv[i].x*kv[j].x + qv[i].y*kv[j].y + qv[i].z*kv[j].z + qv[i].w*kv[j].w;
        }
        __syncthreads();   // all threads done reading K tile

        // online softmax; write P into KPs
        #pragma unroll
        for (int i = 0; i < 4; i++) {
            float mx = fmaxf(fmaxf(s[i][0], s[i][1]), fmaxf(s[i][2], s[i][3]));
            #pragma unroll
            for (int o = 8; o; o >>= 1) mx = fmaxf(mx, __shfl_xor_sync(0xffffffffu, mx, o, 16));
            float mn = fmaxf(m[i], mx);
            float co = __expf(m[i] - mn);
            m[i] = mn;
            float p0 = __expf(s[i][0] - mn);
            float p1 = __expf(s[i][1] - mn);
            float p2 = __expf(s[i][2] - mn);
            float p3 = __expf(s[i][3] - mn);
            float rs = p0 + p1 + p2 + p3;
            #pragma unroll
            for (int o = 8; o; o >>= 1) rs += __shfl_xor_sync(0xffffffffu, rs, o, 16);
            l[i] = l[i] * co + rs;
            acc[i].x *= co; acc[i].y *= co; acc[i].z *= co; acc[i].w *= co;
            *(float4*)&KPs[(q0 + i) * ATT_LD + tx * 4] = make_float4(p0, p1, p2, p3);
        }
        __syncthreads();

        // O += P V
        #pragma unroll
        for (int j4 = 0; j4 < 16; j4++) {
            float4 vr[4];
            #pragma unroll
            for (int jj = 0; jj < 4; jj++)
                vr[jj] = *(const float4*)&Vs[(j4*4 + jj) * ATT_LD + tx * 4];
            #pragma unroll
            for (int i = 0; i < 4; i++) {
                float4 pv = *(const float4*)&KPs[(q0 + i) * ATT_LD + j4 * 4];
                acc[i].x += pv.x*vr[0].x + pv.y*vr[1].x + pv.z*vr[2].x + pv.w*vr[3].x;
                acc[i].y += pv.x*vr[0].y + pv.y*vr[1].y + pv.z*vr[2].y + pv.w*vr[3].y;
                acc[i].z += pv.x*vr[0].z + pv.y*vr[1].z + pv.z*vr[2].z + pv.w*vr[3].z;
                acc[i].w += pv.x*vr[0].w + pv.y*vr[1].w + pv.z*vr[2].w + pv.w*vr[3].w;
            }
        }
        __syncthreads();
    }

    #pragma unroll
    for (int i = 0; i < 4; i++) {
        float inv = 1.0f / l[i];
        float4 o = acc[i];
        o.x *= inv; o.y *= inv; o.z *= inv; o.w *= inv;
        *(float4*)(O + (rowbase + qb*64 + q0 + i) * 1024 + colbase + tx * 4) = o;
    }
}

// ---------------- host launcher ----------------
extern "C" void kernel_launch(void* const* d_in, const int* in_sizes, int n_in,
                              void* d_out, int out_size) {
    const float* x    = (const float*)d_in[0];
    const float* WQ   = (const float*)d_in[1];
    const float* WK   = (const float*)d_in[2];
    const float* WV   = (const float*)d_in[3];
    const float* WO   = (const float*)d_in[4];
    const float* ln1g = (const float*)d_in[5];
    const float* ln1b = (const float*)d_in[6];
    const float* ln2g = (const float*)d_in[7];
    const float* ln2b = (const float*)d_in[8];
    const float* w1   = (const float*)d_in[9];
    const float* b1   = (const float*)d_in[10];
    const float* w2   = (const float*)d_in[11];
    const float* b2   = (const float*)d_in[12];
    float* out = (float*)d_out;

    float *normx, *q, *k, *v, *attn, *x1, *hb, *h1;
    cudaGetSymbolAddress((void**)&normx, g_normx);
    cudaGetSymbolAddress((void**)&q,     g_q);
    cudaGetSymbolAddress((void**)&k,     g_k);
    cudaGetSymbolAddress((void**)&v,     g_v);
    cudaGetSymbolAddress((void**)&attn,  g_attn);
    cudaGetSymbolAddress((void**)&x1,    g_x1);
    cudaGetSymbolAddress((void**)&hb,    g_h);
    cudaGetSymbolAddress((void**)&h1,    g_h1);

    const int ATT_SMEM = 3 * 64 * ATT_LD * 4;  // 52224 bytes
    cudaFuncSetAttribute(attn_kernel, cudaFuncAttributeMaxDynamicSharedMemorySize, ATT_SMEM);

    // 1) LN1
    ln_kernel<<<TT, 256>>>(x, ln1g, ln1b, normx);

    // 2) QKV projections (per-head gathered B)
    dim3 gqkv(DD / 128, TT / 128);
    gemm_kernel<true,  false><<<gqkv, 256>>>(normx, WQ, q, TT, DD, DD, nullptr, nullptr);
    gemm_kernel<true,  false><<<gqkv, 256>>>(normx, WK, k, TT, DD, DD, nullptr, nullptr);
    gemm_kernel<true,  false><<<gqkv, 256>>>(normx, WV, v, TT, DD, DD, nullptr, nullptr);

    // 3) attention
    attn_kernel<<<dim3(SS / 64, BB * HH), 256, ATT_SMEM>>>(q, k, v, attn);

    // 4) O projection + residual -> x1
    gemm_kernel<false, false><<<dim3(DD / 128, TT / 128), 256>>>(attn, WO, x1, TT, DD, DD, nullptr, x);

    // 5) LN2
    ln_kernel<<<TT, 256>>>(x1, ln2g, ln2b, hb);

    // 6) MLP1: relu(h @ w1 + b1)
    gemm_kernel<false, true ><<<dim3(DM / 128, TT / 128), 256>>>(hb, w1, h1, TT, DM, DD, b1, nullptr);

    // 7) MLP2: x1 + (h1 @ w2 + b2) -> out
    gemm_kernel<false, false><<<dim3(DD / 128, TT / 128), 256>>>(h1, w2, out, TT, DD, DM, b2, x1);
}

// round 3
// speedup vs baseline: 1.0012x; 1.0005x over previous
#include <cuda_runtime.h>
#include <math.h>

#define BB 2
#define SS 2048
#define TT (BB*SS)
#define DD 1024
#define HH 16
#define DHH 64
#define DM 4096

// ---------------- scratch (device globals; no runtime allocation) ----------------
__device__ float g_normx[TT*DD];
__device__ float g_q[TT*DD];
__device__ float g_k[TT*DD];
__device__ float g_v[TT*DD];
__device__ float g_attn[TT*DD];
__device__ float g_x1[TT*DD];
__device__ float g_h[TT*DD];
__device__ float g_h1[(size_t)TT*DM];

// ---------------- LayerNorm: one block per token ----------------
__global__ void __launch_bounds__(256) ln_kernel(const float* __restrict__ x,
                                                 const float* __restrict__ g,
                                                 const float* __restrict__ be,
                                                 float* __restrict__ out) {
    int t = blockIdx.x;
    int tid = threadIdx.x;
    float4 v = ((const float4*)(x + (size_t)t * DD))[tid];
    float s  = v.x + v.y + v.z + v.w;
    float ss = v.x*v.x + v.y*v.y + v.z*v.z + v.w*v.w;
    #pragma unroll
    for (int o = 16; o; o >>= 1) {
        s  += __shfl_xor_sync(0xffffffffu, s, o);
        ss += __shfl_xor_sync(0xffffffffu, ss, o);
    }
    __shared__ float ws[8], wss[8];
    int w = tid >> 5, ln = tid & 31;
    if (ln == 0) { ws[w] = s; wss[w] = ss; }
    __syncthreads();
    float ts = 0.f, tss = 0.f;
    #pragma unroll
    for (int i = 0; i < 8; i++) { ts += ws[i]; tss += wss[i]; }
    float mu  = ts * (1.0f / DD);
    float var = tss * (1.0f / DD) - mu * mu;
    float rs  = rsqrtf(var + 1e-5f);
    float4 gv = ((const float4*)g)[tid];
    float4 bv = ((const float4*)be)[tid];
    float4 o;
    o.x = (v.x - mu) * rs * gv.x + bv.x;
    o.y = (v.y - mu) * rs * gv.y + bv.y;
    o.z = (v.z - mu) * rs * gv.z + bv.z;
    o.w = (v.w - mu) * rs * gv.w + bv.w;
    ((float4*)(out + (size_t)t * DD))[tid] = o;
}

// ---------------- GEMM: C[M,N] = A[M,K] @ B[K,N] (+bias)(+relu)(+res) ----------------
// HEADB: B is [H][K][64] per-head layout, logical column j -> W[j>>6][k][j&63]
template<bool HEADB, bool RELU>
__global__ void __launch_bounds__(256) gemm_kernel(
    const float* __restrict__ A, const float* __restrict__ Bm,
    float* __restrict__ C, int M, int N, int K,
    const float* __restrict__ bias, const float* __restrict__ res)
{
    __shared__ float As[8][132];   // transposed, padded (conflict-free)
    __shared__ float Bs[8][128];
    const int tid = threadIdx.x;
    const int bm = blockIdx.y, bn = blockIdx.x;

    const int arow = tid >> 1;          // 0..127
    const int acol = (tid & 1) << 2;    // 0 or 4
    const float* Ap = A + (size_t)(bm * 128 + arow) * K + acol;

    const int brow = tid >> 5;          // 0..7
    const int bcol = (tid & 31) << 2;   // 0..124
    const int gcol = bn * 128 + bcol;
    const float* Bp;
    int ldb;
    if (HEADB) { ldb = 64; Bp = Bm + (size_t)(gcol >> 6) * K * 64 + (gcol & 63) + (size_t)brow * 64; }
    else       { ldb = N;  Bp = Bm + (size_t)brow * N + gcol; }

    const int ra = (tid >> 4) << 2;     // 0..60
    const int cb = (tid & 15) << 2;     // 0..60

    float acc[8][8];
    #pragma unroll
    for (int i = 0; i < 8; i++)
        #pragma unroll
        for (int j = 0; j < 8; j++) acc[i][j] = 0.f;

    for (int k0 = 0; k0 < K; k0 += 8) {
        float4 av = *(const float4*)(Ap + k0);
        As[acol + 0][arow] = av.x;
        As[acol + 1][arow] = av.y;
        As[acol + 2][arow] = av.z;
        As[acol + 3][arow] = av.w;
        *(float4*)&Bs[brow][bcol] = *(const float4*)(Bp + (size_t)k0 * ldb);
        __syncthreads();
        #pragma unroll
        for (int kk = 0; kk < 8; kk++) {
            float4 a0 = *(const float4*)&As[kk][ra];
            float4 a1 = *(const float4*)&As[kk][ra + 64];
            float4 b0 = *(const float4*)&Bs[kk][cb];
            float4 b1 = *(const float4*)&Bs[kk][cb + 64];
            float a[8] = {a0.x,a0.y,a0.z,a0.w,a1.x,a1.y,a1.z,a1.w};
            float b[8] = {b0.x,b0.y,b0.z,b0.w,b1.x,b1.y,b1.z,b1.w};
            #pragma unroll
            for (int i = 0; i < 8; i++)
                #pragma unroll
                for (int j = 0; j < 8; j++)
                    acc[i][j] = fmaf(a[i], b[j], acc[i][j]);
        }
        __syncthreads();
    }

    #pragma unroll
    for (int i = 0; i < 8; i++) {
        int r = bm * 128 + ra + (i < 4 ? i : 60 + i);
        #pragma unroll
        for (int jh = 0; jh < 2; jh++) {
            int c = bn * 128 + cb + jh * 64;
            float4 v;
            v.x = acc[i][jh*4+0]; v.y = acc[i][jh*4+1];
            v.z = acc[i][jh*4+2]; v.w = acc[i][jh*4+3];
            if (bias) {
                float4 bb = *(const float4*)(bias + c);
                v.x += bb.x; v.y += bb.y; v.z += bb.z; v.w += bb.w;
            }
            if (RELU) {
                v.x = fmaxf(v.x, 0.f); v.y = fmaxf(v.y, 0.f);
                v.z = fmaxf(v.z, 0.f); v.w = fmaxf(v.w, 0.f);
            }
            if (res) {
                float4 rv = *(const float4*)(res + (size_t)r * N + c);
                v.x += rv.x; v.y += rv.y; v.z += rv.z; v.w += rv.w;
            }
            *(float4*)(C + (size_t)r * N + c) = v;
        }
    }
}

// ---------------- Flash-style attention, fp32, BQ=BK=64 ----------------
// Q/K/V layout: [T][1024] with columns h*64..h*64+63 per head.
#define ATT_LD 68
__global__ void __launch_bounds__(256) attn_kernel(
    const float* __restrict__ Q, const float* __restrict__ Km,
    const float* __restrict__ V, float* __restrict__ O)
{
    extern __shared__ float sm[];
    float* Qs  = sm;                 // 64 x 68
    float* KPs = sm + 64 * ATT_LD;   // K tile, later reused for P
    float* Vs  = sm + 2 * 64 * ATT_LD;

    const int tid = threadIdx.x;
    const int qb = blockIdx.x, bh = blockIdx.y;
    const int b = bh >> 4, h = bh & 15;
    const int colbase = h * 64;
    const size_t rowbase = (size_t)b * SS;

    #pragma unroll
    for (int i = 0; i < 4; i++) {
        int idx = tid + i * 256;
        int row = idx >> 4;
        int c4  = (idx & 15) << 2;
        float4 qv = *(const float4*)(Q + (rowbase + qb*64 + row) * 1024 + colbase + c4);
        qv.x *= 0.125f; qv.y *= 0.125f; qv.z *= 0.125f; qv.w *= 0.125f;  // 1/sqrt(64)
        *(float4*)&Qs[row * ATT_LD + c4] = qv;
    }

    const int ty = tid >> 4, tx = tid & 15;
    const int q0 = ty << 2;
    float m[4] = {-1e30f, -1e30f, -1e30f, -1e30f};
    float l[4] = {0.f, 0.f, 0.f, 0.f};
    float4 acc[4];
    #pragma unroll
    for (int i = 0; i < 4; i++) acc[i] = make_float4(0.f, 0.f, 0.f, 0.f);

    __syncthreads();

    for (int kb = 0; kb < SS / 64; kb++) {
        #pragma unroll
        for (int i = 0; i < 4; i++) {
            int idx = tid + i * 256;
            int row = idx >> 4;
            int c4  = (idx & 15) << 2;
            size_t gro = (rowbase + kb*64 + row) * 1024 + colbase + c4;
            *(float4*)&KPs[row * ATT_LD + c4] = *(const float4*)(Km + gro);
            *(float4*)&Vs [row * ATT_LD + c4] = *(const float4*)(V  + gro);
        }
        __syncthreads();

        // S = Q K^T for this thread's 4x4 patch
        float s[4][4] = {};
        #pragma unroll
        for (int dv = 0; dv < 16; dv++) {
            float4 qv[4], kv[4];
            #pragma unroll
            for (int i = 0; i < 4; i++) qv[i] = *(const float4*)&Qs[(q0 + i) * ATT_LD + dv * 4];
            #pragma unroll
            for (int j = 0; j < 4; j++) kv[j] = *(const float4*)&KPs[(tx*4 + j) * ATT_LD + dv * 4];
            #pragma unroll
            for (int i = 0; i < 4; i++)
                #pragma unroll
                for (int j = 0; j < 4; j++)
                    s[i][j] += qv[i].x*kv[j].x + qv[i].y*kv[j].y + qv[i].z*kv[j].z + qv[i].w*kv[j].w;
        }
        __syncthreads();   // all threads done reading K tile

        // online softmax; write P into KPs
        #pragma unroll
        for (int i = 0; i < 4; i++) {
            float mx = fmaxf(fmaxf(s[i][0], s[i][1]), fmaxf(s[i][2], s[i][3]));
            #pragma unroll
            for (int o = 8; o; o >>= 1) mx = fmaxf(mx, __shfl_xor_sync(0xffffffffu, mx, o, 16));
            float mn = fmaxf(m[i], mx);
            float co = __expf(m[i] - mn);
            m[i] = mn;
            float p0 = __expf(s[i][0] - mn);
            float p1 = __expf(s[i][1] - mn);
            float p2 = __expf(s[i][2] - mn);
            float p3 = __expf(s[i][3] - mn);
            float rs = p0 + p1 + p2 + p3;
            #pragma unroll
            for (int o = 8; o; o >>= 1) rs += __shfl_xor_sync(0xffffffffu, rs, o, 16);
            l[i] = l[i] * co + rs;
            acc[i].x *= co; acc[i].y *= co; acc[i].z *= co; acc[i].w *= co;
            *(float4*)&KPs[(q0 + i) * ATT_LD + tx * 4] = make_float4(p0, p1, p2, p3);
        }
        __syncthreads();

        // O += P V
        #pragma unroll
        for (int j4 = 0; j4 < 16; j4++) {
            float4 vr[4];
            #pragma unroll
            for (int jj = 0; jj < 4; jj++)
                vr[jj] = *(const float4*)&Vs[(j4*4 + jj) * ATT_LD + tx * 4];
            #pragma unroll
            for (int i = 0; i < 4; i++) {
                float4 pv = *(const float4*)&KPs[(q0 + i) * ATT_LD + j4 * 4];
                acc[i].x += pv.x*vr[0].x + pv.y*vr[1].x + pv.z*vr[2].x + pv.w*vr[3].x;
                acc[i].y += pv.x*vr[0].y + pv.y*vr[1].y + pv.z*vr[2].y + pv.w*vr[3].y;
                acc[i].z += pv.x*vr[0].z + pv.y*vr[1].z + pv.z*vr[2].z + pv.w*vr[3].z;
                acc[i].w += pv.x*vr[0].w + pv.y*vr[1].w + pv.z*vr[2].w + pv.w*vr[3].w;
            }
        }
        __syncthreads();
    }

    #pragma unroll
    for (int i = 0; i < 4; i++) {
        float inv = 1.0f / l[i];
        float4 o = acc[i];
        o.x *= inv; o.y *= inv; o.z *= inv; o.w *= inv;
        *(float4*)(O + (rowbase + qb*64 + q0 + i) * 1024 + colbase + tx * 4) = o;
    }
}

// ---------------- host launcher ----------------
extern "C" void kernel_launch(void* const* d_in, const int* in_sizes, int n_in,
                              void* d_out, int out_size) {
    const float* x    = (const float*)d_in[0];
    const float* WQ   = (const float*)d_in[1];
    const float* WK   = (const float*)d_in[2];
    const float* WV   = (const float*)d_in[3];
    const float* WO   = (const float*)d_in[4];
    const float* ln1g = (const float*)d_in[5];
    const float* ln1b = (const float*)d_in[6];
    const float* ln2g = (const float*)d_in[7];
    const float* ln2b = (const float*)d_in[8];
    const float* w1   = (const float*)d_in[9];
    const float* b1   = (const float*)d_in[10];
    const float* w2   = (const float*)d_in[11];
    const float* b2   = (const float*)d_in[12];
    float* out = (float*)d_out;

    float *normx, *q, *k, *v, *attn, *x1, *hb, *h1;
    cudaGetSymbolAddress((void**)&normx, g_normx);
    cudaGetSymbolAddress((void**)&q,     g_q);
    cudaGetSymbolAddress((void**)&k,     g_k);
    cudaGetSymbolAddress((void**)&v,     g_v);
    cudaGetSymbolAddress((void**)&attn,  g_attn);
    cudaGetSymbolAddress((void**)&x1,    g_x1);
    cudaGetSymbolAddress((void**)&hb,    g_h);
    cudaGetSymbolAddress((void**)&h1,    g_h1);

    const int ATT_SMEM = 3 * 64 * ATT_LD * 4;  // 52224 bytes
    cudaFuncSetAttribute(attn_kernel, cudaFuncAttributeMaxDynamicSharedMemorySize, ATT_SMEM);

    // 1) LN1
    ln_kernel<<<TT, 256>>>(x, ln1g, ln1b, normx);

    // 2) QKV projections (per-head gathered B)
    dim3 gqkv(DD / 128, TT / 128);
    gemm_kernel<true,  false><<<gqkv, 256>>>(normx, WQ, q, TT, DD, DD, nullptr, nullptr);
    gemm_kernel<true,  false><<<gqkv, 256>>>(normx, WK, k, TT, DD, DD, nullptr, nullptr);
    gemm_kernel<true,  false><<<gqkv, 256>>>(normx, WV, v, TT, DD, DD, nullptr, nullptr);

    // 3) attention
    attn_kernel<<<dim3(SS / 64, BB * HH), 256, ATT_SMEM>>>(q, k, v, attn);

    // 4) O projection + residual -> x1
    gemm_kernel<false, false><<<dim3(DD / 128, TT / 128), 256>>>(attn, WO, x1, TT, DD, DD, nullptr, x);

    // 5) LN2
    ln_kernel<<<TT, 256>>>(x1, ln2g, ln2b, hb);

    // 6) MLP1: relu(h @ w1 + b1)
    gemm_kernel<false, true ><<<dim3(DM / 128, TT / 128), 256>>>(hb, w1, h1, TT, DM, DD, b1, nullptr);

    // 7) MLP2: x1 + (h1 @ w2 + b2) -> out
    gemm_kernel<false, false><<<dim3(DD / 128, TT / 128), 256>>>(h1, w2, out, TT, DD, DM, b2, x1);
}